// round 4
// baseline (speedup 1.0000x reference)
#include <cuda_runtime.h>
#include <cuda_bf16.h>

#define N_CELLS   776
#define N_ANCHORS 3
#define N_CH      7
#define CONF_THRESH 0.8f
#define NO_OBJECT   0.5f

#define GRID      8
#define BLOCK     128
#define CPB       97                  // cells per block: 8*97 = 776 exactly
#define FPB       (CPB * N_ANCHORS * N_CH)   // 2037 floats per block

__device__ float        g_partials[GRID];
__device__ unsigned int g_count = 0;

__global__ __launch_bounds__(BLOCK, 1)
void yolo_loss_kernel(const float* __restrict__ pred,
                      const float* __restrict__ label,
                      float* __restrict__ out)
{
    __shared__ float s[FPB];
    __shared__ float warp_sums[BLOCK / 32];

    const int tid = threadIdx.x;
    const int bid = blockIdx.x;

    // Coalesced stage: contiguous slice of pred -> shared. 16 independent
    // loads per thread (MLP=16), each warp-load hits exactly 1 cache line.
    const float* __restrict__ src = pred + (size_t)bid * FPB;
    #pragma unroll
    for (int i = tid; i < FPB; i += BLOCK)
        s[i] = src[i];

    // Label broadcast (7 floats, L1-resident after first warp).
    const float lx = __ldg(&label[0]);
    const float ly = __ldg(&label[1]);
    const float lw = __ldg(&label[2]);
    const float lh = __ldg(&label[3]);
    const float lc = __ldg(&label[4]);
    const float l5 = __ldg(&label[5]);
    const float l6 = __ldg(&label[6]);

    const float lw2    = lw * 0.5f, lh2 = lh * 0.5f;
    const float area_b = fabsf(lw * lh);

    __syncthreads();

    float loss = 0.0f;

    if (tid < CPB) {
        // SMEM base stride 21 floats; gcd(21,32)=1 -> conflict-free LDS.
        const float* p0 = s + tid * (N_ANCHORS * N_CH);

        float best_iou = -1.0f;
        float b0 = 0.f, b1 = 0.f, b4 = 0.f, b5 = 0.f, b6 = 0.f;

        #pragma unroll
        for (int a = 0; a < N_ANCHORS; ++a) {
            const float* p = p0 + a * N_CH;
            float px = p[0], py = p[1], pw = p[2], ph = p[3];
            float pc = p[4], p5 = p[5], p6 = p[6];

            float pw2 = pw * 0.5f, ph2 = ph * 0.5f;
            float ax = fmaxf(px - pw2, lx - lw2);
            float ay = fmaxf(py - ph2, ly - lh2);
            float bx = fminf(px + pw2, lx + lw2);
            float by = fminf(py + ph2, ly + lh2);
            float inter  = fabsf(fmaxf(bx - ax, 0.0f) * fmaxf(by - ay, 0.0f));
            float area_a = fabsf(pw * ph);
            float iou = inter / (area_a + area_b - inter);

            // jnp.argmax keeps the FIRST max on ties -> strict >
            if (iou > best_iou) {
                best_iou = iou;
                b0 = px; b1 = py; b4 = pc; b5 = p5; b6 = p6;
            }
        }

        float dx = lx - b0, dy = ly - b1;
        float xy_loss = dx * dx + dy * dy;
        // Reference compares sqrt(label[0,1]) vs sqrt(best[:,0,1]) — replicate.
        float swx = sqrtf(lx) - sqrtf(b0);
        float swy = sqrtf(ly) - sqrtf(b1);
        float wh_loss = swx * swx + swy * swy;
        float coord_loss = xy_loss + wh_loss;

        bool  has_obj = b4 > CONF_THRESH;
        float d5 = l5 - b5, d6 = l6 - b6;
        float class_loss = has_obj ? (d5 * d5 + d6 * d6) : 0.0f;
        float dc = lc - b4;
        float conf_sq = dc * dc;
        float conf_loss = has_obj ? conf_sq : NO_OBJECT * conf_sq;

        loss = coord_loss + class_loss + conf_loss;
    }

    // Deterministic in-block reduction: fixed-order butterfly + serial 4-way.
    #pragma unroll
    for (int off = 16; off > 0; off >>= 1)
        loss += __shfl_down_sync(0xFFFFFFFFu, loss, off);

    const int warp = tid >> 5;
    const int lane = tid & 31;
    if (lane == 0) warp_sums[warp] = loss;
    __syncthreads();

    if (tid == 0) {
        float part = 0.0f;
        #pragma unroll
        for (int w = 0; w < BLOCK / 32; ++w) part += warp_sums[w];
        g_partials[bid] = part;
        __threadfence();

        unsigned int ticket = atomicAdd(&g_count, 1u);
        if (ticket == GRID - 1) {
            // All partials are globally visible (fence before each increment).
            volatile float* vp = g_partials;
            float total = 0.0f;
            #pragma unroll
            for (int b = 0; b < GRID; ++b) total += vp[b];   // fixed order
            out[0] = total;
            g_count = 0;   // reset for next graph replay (deterministic state)
        }
    }
}

extern "C" void kernel_launch(void* const* d_in, const int* in_sizes, int n_in,
                              void* d_out, int out_size)
{
    const float* pred  = (const float*)d_in[0];
    const float* label = (const float*)d_in[1];
    float* out = (float*)d_out;
    yolo_loss_kernel<<<GRID, BLOCK>>>(pred, label, out);
}

// round 7
// speedup vs baseline: 1.4904x; 1.4904x over previous
#include <cuda_runtime.h>
#include <cuda_bf16.h>

#define N_CELLS   776
#define N_ANCHORS 3
#define N_CH      7
#define CONF_THRESH 0.8f
#define NO_OBJECT   0.5f

#define NTHREADS  800                      // 25 warps, 1 thread per cell
#define NFLOATS   (N_CELLS * N_ANCHORS * N_CH)   // 16296
#define NVEC4     (NFLOATS / 4)                  // 4074 (exact)

__global__ __launch_bounds__(NTHREADS, 1)
void yolo_loss_kernel(const float4* __restrict__ pred4,
                      const float* __restrict__ label,
                      float* __restrict__ out)
{
    __shared__ float s[NFLOATS];
    __shared__ float warp_sums[NTHREADS / 32];

    const int tid = threadIdx.x;

    // Coalesced vectorized stage: 4074 float4 loads across 800 threads
    // (~5 iters/thread, each warp-load = 4 consecutive 128B lines, MLP high).
    float4* __restrict__ s4 = reinterpret_cast<float4*>(s);
    #pragma unroll
    for (int i = tid; i < NVEC4; i += NTHREADS)
        s4[i] = pred4[i];

    // Label broadcast (7 floats).
    const float lx = __ldg(&label[0]);
    const float ly = __ldg(&label[1]);
    const float lw = __ldg(&label[2]);
    const float lh = __ldg(&label[3]);
    const float lc = __ldg(&label[4]);
    const float l5 = __ldg(&label[5]);
    const float l6 = __ldg(&label[6]);

    const float lw2    = lw * 0.5f, lh2 = lh * 0.5f;
    const float area_b = fabsf(lw * lh);

    __syncthreads();

    float loss = 0.0f;

    if (tid < N_CELLS) {
        // SMEM stride 21 floats; gcd(21,32)=1 -> bank-conflict-free.
        const float* p0 = s + tid * (N_ANCHORS * N_CH);

        float best_iou = -1.0f;
        float b0 = 0.f, b1 = 0.f, b4 = 0.f, b5 = 0.f, b6 = 0.f;

        #pragma unroll
        for (int a = 0; a < N_ANCHORS; ++a) {
            const float* p = p0 + a * N_CH;
            float px = p[0], py = p[1], pw = p[2], ph = p[3];
            float pc = p[4], p5 = p[5], p6 = p[6];

            float pw2 = pw * 0.5f, ph2 = ph * 0.5f;
            float ax = fmaxf(px - pw2, lx - lw2);
            float ay = fmaxf(py - ph2, ly - lh2);
            float bx = fminf(px + pw2, lx + lw2);
            float by = fminf(py + ph2, ly + lh2);
            float inter  = fabsf(fmaxf(bx - ax, 0.0f) * fmaxf(by - ay, 0.0f));
            float area_a = fabsf(pw * ph);
            float iou = inter / (area_a + area_b - inter);

            // jnp.argmax keeps the FIRST max on ties -> strict >
            if (iou > best_iou) {
                best_iou = iou;
                b0 = px; b1 = py; b4 = pc; b5 = p5; b6 = p6;
            }
        }

        float dx = lx - b0, dy = ly - b1;
        float xy_loss = dx * dx + dy * dy;
        // Reference compares sqrt(label[0,1]) vs sqrt(best[:,0,1]) — replicate.
        float swx = sqrtf(lx) - sqrtf(b0);
        float swy = sqrtf(ly) - sqrtf(b1);
        float wh_loss = swx * swx + swy * swy;
        float coord_loss = xy_loss + wh_loss;

        bool  has_obj = b4 > CONF_THRESH;
        float d5 = l5 - b5, d6 = l6 - b6;
        float class_loss = has_obj ? (d5 * d5 + d6 * d6) : 0.0f;
        float dc = lc - b4;
        float conf_sq = dc * dc;
        float conf_loss = has_obj ? conf_sq : NO_OBJECT * conf_sq;

        loss = coord_loss + class_loss + conf_loss;
    }

    // Deterministic reduction: fixed-order warp butterfly, then thread 0
    // serially sums the 25 warp partials. No atomics, no global state.
    #pragma unroll
    for (int off = 16; off > 0; off >>= 1)
        loss += __shfl_down_sync(0xFFFFFFFFu, loss, off);

    const int warp = tid >> 5;
    const int lane = tid & 31;
    if (lane == 0) warp_sums[warp] = loss;
    __syncthreads();

    if (tid == 0) {
        float total = 0.0f;
        #pragma unroll
        for (int w = 0; w < NTHREADS / 32; ++w) total += warp_sums[w];
        out[0] = total;
    }
}

extern "C" void kernel_launch(void* const* d_in, const int* in_sizes, int n_in,
                              void* d_out, int out_size)
{
    const float4* pred4 = (const float4*)d_in[0];
    const float*  label = (const float*)d_in[1];
    float* out = (float*)d_out;
    yolo_loss_kernel<<<1, NTHREADS>>>(pred4, label, out);
}